// round 8
// baseline (speedup 1.0000x reference)
#include <cuda_runtime.h>
#include <cuda_bf16.h>
#include <math.h>
#include <stdint.h>

typedef __nv_bfloat16 bf16;

#define BQ 2
#define TQ 2048
#define DMODEL 1024
#define DINNER 2048
#define NHEADS 32
#define DHEAD 64
#define DCONV 4
#define PROJ_OUT 4224
#define BT 4096
#define PARAM_OFF 4096
#define BC_OFF 4160
#define DFF 4096

// ---------------- scratch (device globals; no allocation) ----------------
__device__ float g_proj[(size_t)BT * PROJ_OUT];
__device__ float g_val [(size_t)BT * DINNER];
__device__ float g_par [(size_t)BT * NHEADS * 2];
__device__ float g_bcT [(size_t)BT * 64];
__device__ float g_scan[(size_t)BT * DINNER];
__device__ float g_x1  [BT * DMODEL];
__device__ bf16 g_h1h[BT * DMODEL],         g_h1l[BT * DMODEL];
__device__ bf16 g_ygh[(size_t)BT * DINNER], g_ygl[(size_t)BT * DINNER];
__device__ bf16 g_h2h[BT * DMODEL],         g_h2l[BT * DMODEL];
__device__ bf16 g_ffh[(size_t)BT * DFF],    g_ffl[(size_t)BT * DFF];
__device__ bf16 g_winh[PROJ_OUT * 1024],    g_winl[PROJ_OUT * 1024];
__device__ bf16 g_woh [1024 * 2048],        g_wol [1024 * 2048];
__device__ bf16 g_w1h [4096 * 1024],        g_w1l [4096 * 1024];
__device__ bf16 g_w2h [1024 * 4096],        g_w2l [1024 * 4096];

// ---------------- math helpers ----------------
__device__ __forceinline__ float sigmoidf_(float x) { return 1.f / (1.f + __expf(-x)); }
__device__ __forceinline__ float siluf_(float x)    { return x / (1.f + __expf(-x)); }
__device__ __forceinline__ float geluf_(float x) {
    float x3 = x * x * x;
    return 0.5f * x * (1.f + tanhf(0.7978845608028654f * (x + 0.044715f * x3)));
}
__device__ __forceinline__ float softplusf_(float x) {
    return (x > 20.f) ? x : log1pf(expf(x));
}

__device__ __forceinline__ float block_reduce_sum(float v) {
    __shared__ float sh[32];
    int lane = threadIdx.x & 31, wid = threadIdx.x >> 5;
    int nwarps = blockDim.x >> 5;
    #pragma unroll
    for (int m = 16; m > 0; m >>= 1) v += __shfl_xor_sync(0xffffffffu, v, m);
    if (lane == 0) sh[wid] = v;
    __syncthreads();
    if (wid == 0) {
        v = (lane < nwarps) ? sh[lane] : 0.f;
        #pragma unroll
        for (int m = 16; m > 0; m >>= 1) v += __shfl_xor_sync(0xffffffffu, v, m);
        if (lane == 0) sh[0] = v;
    }
    __syncthreads();
    return sh[0];
}

// ---------------- low-level (sm_80-compatible only) ----------------
__device__ __forceinline__ uint32_t smem_u32(const void* p) {
    uint32_t a;
    asm("{ .reg .u64 t; cvta.to.shared.u64 t, %1; cvt.u32.u64 %0, t; }" : "=r"(a) : "l"(p));
    return a;
}
#define CP_ASYNC16(dst, src) \
    asm volatile("cp.async.cg.shared.global [%0], [%1], 16;" :: "r"((uint32_t)(dst)), "l"(src))
#define CP_COMMIT() asm volatile("cp.async.commit_group;" ::: "memory")

__device__ __forceinline__ void ldsm_x4(uint32_t* r, uint32_t addr) {
    asm volatile("ldmatrix.sync.aligned.m8n8.x4.shared.b16 {%0,%1,%2,%3}, [%4];"
                 : "=r"(r[0]), "=r"(r[1]), "=r"(r[2]), "=r"(r[3]) : "r"(addr));
}
__device__ __forceinline__ void ldsm_x2(uint32_t* r, uint32_t addr) {
    asm volatile("ldmatrix.sync.aligned.m8n8.x2.shared.b16 {%0,%1}, [%2];"
                 : "=r"(r[0]), "=r"(r[1]) : "r"(addr));
}
__device__ __forceinline__ void mma16816(float* c, const uint32_t* a, const uint32_t* b) {
    asm volatile("mma.sync.aligned.m16n8k16.row.col.f32.bf16.bf16.f32 "
                 "{%0,%1,%2,%3}, {%4,%5,%6,%7}, {%8,%9}, {%0,%1,%2,%3};"
                 : "+f"(c[0]), "+f"(c[1]), "+f"(c[2]), "+f"(c[3])
                 : "r"(a[0]), "r"(a[1]), "r"(a[2]), "r"(a[3]), "r"(b[0]), "r"(b[1]));
}

// ---------------- rmsnorm + bf16 split ----------------
__global__ void rmsnorm_split_kernel(const float* __restrict__ x, const float* __restrict__ w,
                                     bf16* __restrict__ oh, bf16* __restrict__ ol, int D) {
    int row = blockIdx.x;
    const float* xr = x + (size_t)row * D;
    float ss = 0.f;
    for (int i = threadIdx.x; i < D; i += blockDim.x) { float v = xr[i]; ss += v * v; }
    ss = block_reduce_sum(ss);
    float inv = rsqrtf(ss / (float)D + 1e-6f);
    for (int i = threadIdx.x; i < D; i += blockDim.x) {
        float v = xr[i] * inv * w[i];
        bf16 h = __float2bfloat16(v);
        oh[(size_t)row * D + i] = h;
        ol[(size_t)row * D + i] = __float2bfloat16(v - __bfloat162float(h));
    }
}

// ---------------- gated rmsnorm + split ----------------
__global__ void gated_norm_split_kernel(const float* __restrict__ proj, const float* __restrict__ scan_y,
                                        const float* __restrict__ w,
                                        bf16* __restrict__ oh, bf16* __restrict__ ol) {
    __shared__ float buf[DINNER];
    int row = blockIdx.x;
    const float* prow = proj + (size_t)row * PROJ_OUT;
    const float* sy = scan_y + (size_t)row * DINNER;
    float ss = 0.f;
    for (int i = threadIdx.x; i < DINNER; i += blockDim.x) {
        float t = sy[i] * siluf_(prow[i]);
        buf[i] = t; ss += t * t;
    }
    ss = block_reduce_sum(ss);
    float inv = rsqrtf(ss / (float)DINNER + 1e-6f);
    for (int i = threadIdx.x; i < DINNER; i += blockDim.x) {
        float v = buf[i] * inv * w[i];
        bf16 h = __float2bfloat16(v);
        oh[(size_t)row * DINNER + i] = h;
        ol[(size_t)row * DINNER + i] = __float2bfloat16(v - __bfloat162float(h));
    }
}

// ---------------- fp32 -> bf16 hi/lo split (weights) ----------------
__global__ void split_kernel(const float* __restrict__ src, bf16* __restrict__ hi,
                             bf16* __restrict__ lo, int n) {
    int i = blockIdx.x * blockDim.x + threadIdx.x;
    if (i >= n) return;
    float v = src[i];
    bf16 h = __float2bfloat16(v);
    hi[i] = h;
    lo[i] = __float2bfloat16(v - __bfloat162float(h));
}

// ---------------- fused conv+silu / params / bcpack ----------------
// one block per (b,t) row
__global__ void prep_kernel(const float* __restrict__ proj, const float* __restrict__ conv_w,
                            const float* __restrict__ conv_b, float* __restrict__ value,
                            float* __restrict__ par, float* __restrict__ bcT) {
    int bt = blockIdx.x;
    int t = bt & (TQ - 1);
    int tid = threadIdx.x;
    const float* prow = proj + (size_t)bt * PROJ_OUT;
    // conv + silu: 2048 channels, 8 per thread
    #pragma unroll
    for (int i = 0; i < 8; ++i) {
        int c = tid + i * 256;
        float acc = conv_b[c];
        #pragma unroll
        for (int k = 0; k < DCONV; ++k) {
            int ts = t - (DCONV - 1) + k;
            if (ts >= 0)
                acc += prow[(ts - t) * (ptrdiff_t)PROJ_OUT + DINNER + c] * conv_w[c * DCONV + k];
        }
        value[(size_t)bt * DINNER + c] = siluf_(acc);
    }
    if (tid < 32) {
        int h = tid;
        par[((size_t)bt * NHEADS + h) * 2 + 0] = softplusf_(prow[PARAM_OFF + 2 * h]);
        par[((size_t)bt * NHEADS + h) * 2 + 1] = sigmoidf_(prow[PARAM_OFF + 2 * h + 1]);
    } else if (tid >= 64 && tid < 80) {
        int n = tid - 64;
        float4 v;
        v.x = prow[BC_OFF + n];
        v.y = prow[BC_OFF + 16 + n];
        v.z = prow[BC_OFF + 32 + n];
        v.w = prow[BC_OFF + 48 + n];
        ((float4*)bcT)[(size_t)bt * 16 + n] = v;
    }
}

// ---------------- sequential SSM scan ----------------
__global__ void scan_kernel(const float* __restrict__ bcT, const float* __restrict__ par,
                            const float* __restrict__ value, float* __restrict__ scan_y) {
    int blk = blockIdx.x;
    int bh = blk >> 1;
    int b = bh >> 5;
    int h = bh & 31;
    int half = blk & 1;
    int tid = threadIdx.x;
    int p = half * 32 + (tid >> 4);
    int n = tid & 15;
    float S0 = 0.f, S1 = 0.f;
    const size_t rowbase = (size_t)b * TQ;
    const float4* bc4 = (const float4*)bcT;
    const float2* ad2 = (const float2*)par;
    float4 nbc = bc4[rowbase * 16 + n];
    float2 nad = ad2[rowbase * NHEADS + h];
    float  nu  = value[rowbase * DINNER + h * DHEAD + p];
    for (int t = 0; t < TQ; ++t) {
        float4 bcv = nbc; float2 ad = nad; float u = nu;
        if (t + 1 < TQ) {
            size_t r2 = rowbase + t + 1;
            nbc = bc4[r2 * 16 + n];
            nad = ad2[r2 * NHEADS + h];
            nu  = value[r2 * DINNER + h * DHEAD + p];
        }
        float A = ad.x, dt = ad.y;
        float dtA = dt * A;
        float du = dt * u;
        float s0n = fmaf(-dtA, S1, fmaf(bcv.x, du, S0));
        float s1n = fmaf(dt, S0, fmaf(1.f - dt * dtA, S1, dt * bcv.y * du));
        S0 = s0n; S1 = s1n;
        float y = bcv.z * s0n + bcv.w * s1n;
        y += __shfl_xor_sync(0xffffffffu, y, 8);
        y += __shfl_xor_sync(0xffffffffu, y, 4);
        y += __shfl_xor_sync(0xffffffffu, y, 2);
        y += __shfl_xor_sync(0xffffffffu, y, 1);
        if (n == 0) scan_y[(rowbase + t) * DINNER + h * DHEAD + p] = y;
    }
}

// ---------------- bf16 split-precision GEMM via mma.sync (HMMA) ----------------
// CTA tile 256x128, BK=32, 256 threads (8 warps, 64x64 each), 3-stage cp.async,
// one __syncthreads per chunk. Products Ah*Bh + Ah*Bl + Al*Bh interleaved.
// mode 0: C = acc ; 1: + bias?/res? ; 2: split(gelu(acc+bias)) -> Oh/Ol
#define ATILEB (256 * 80)               // 20480 B (256 rows x 80B)
#define BTILEB (128 * 80)               // 10240 B
#define STAGEB (2 * ATILEB + 2 * BTILEB) // 61440 B
#define NSTAGE 3
#define GEMM_SMEM (NSTAGE * STAGEB)     // 184320
__global__ void __launch_bounds__(256, 1)
gemm_mma(const bf16* __restrict__ Ah, const bf16* __restrict__ Al,
         const bf16* __restrict__ Bh, const bf16* __restrict__ Bl,
         const float* __restrict__ bias, const float* __restrict__ res,
         float* __restrict__ C, bf16* __restrict__ Oh, bf16* __restrict__ Ol,
         int N, int K, int mode) {
    extern __shared__ __align__(16) bf16 dsm[];
    const uint32_t s0 = smem_u32(dsm);
    const int tid = threadIdx.x, wid = tid >> 5, lane = tid & 31;
    const int row0 = blockIdx.y * 256, col0 = blockIdx.x * 128;
    const int wm = wid & 3, wn = wid >> 2;          // 4 x 2 warp grid (64x64 tiles)
    const int nch = K >> 5;

    float acc[4][8][4];
    #pragma unroll
    for (int mt = 0; mt < 4; ++mt)
        #pragma unroll
        for (int nt = 0; nt < 8; ++nt)
            #pragma unroll
            for (int q = 0; q < 4; ++q) acc[mt][nt][q] = 0.f;

    // loader: r = tid>>2 (0..63), c = tid&3 (16B col)
    const int lr = tid >> 2, lc = tid & 3;
    const bf16* gAh = Ah + (size_t)(row0 + lr) * K + lc * 8;
    const bf16* gAl = Al + (size_t)(row0 + lr) * K + lc * 8;
    const bf16* gBh = Bh + (size_t)(col0 + lr) * K + lc * 8;
    const bf16* gBl = Bl + (size_t)(col0 + lr) * K + lc * 8;
    const uint32_t dst = lr * 80 + lc * 16;

    #define LOAD_CHUNK(stg, k0) do {                                                   \
        uint32_t _b = s0 + (stg) * STAGEB + dst;                                       \
        _Pragma("unroll")                                                              \
        for (int q = 0; q < 4; ++q) {                                                  \
            CP_ASYNC16(_b + q * (64 * 80),          gAh + (size_t)(q * 64) * K + (k0));\
            CP_ASYNC16(_b + ATILEB + q * (64 * 80), gAl + (size_t)(q * 64) * K + (k0));\
        }                                                                              \
        _Pragma("unroll")                                                              \
        for (int q = 0; q < 2; ++q) {                                                  \
            CP_ASYNC16(_b + 2 * ATILEB + q * (64 * 80),          gBh + (size_t)(q * 64) * K + (k0)); \
            CP_ASYNC16(_b + 2 * ATILEB + BTILEB + q * (64 * 80), gBl + (size_t)(q * 64) * K + (k0)); \
        }                                                                              \
        CP_COMMIT();                                                                   \
    } while (0)

    LOAD_CHUNK(0, 0);
    LOAD_CHUNK(1, 32);

    const uint32_t a_row = (uint32_t)(wm * 64 + (lane & 15));
    const uint32_t a_coff = (uint32_t)((lane >> 4) * 8);
    const uint32_t b_row = (uint32_t)(wn * 64 + (lane & 7));
    const uint32_t b_coff = (uint32_t)(((lane >> 3) & 1) * 8);

    for (int ch = 0; ch < nch; ++ch) {
        asm volatile("cp.async.wait_group 1;" ::: "memory");
        __syncthreads();                    // stage ch ready; all warps done with ch-1
        if (ch + 2 < nch)
            LOAD_CHUNK((ch + 2) % NSTAGE, (ch + 2) << 5);

        const uint32_t sb = s0 + (ch % NSTAGE) * STAGEB;
        const uint32_t sAh_ = sb, sAl_ = sb + ATILEB;
        const uint32_t sBh_ = sb + 2 * ATILEB, sBl_ = sb + 2 * ATILEB + BTILEB;
        #pragma unroll
        for (int ks = 0; ks < 2; ++ks) {
            const uint32_t acol = (ks * 16 + a_coff) * 2;
            const uint32_t bcol = (ks * 16 + b_coff) * 2;
            uint32_t afr[4][4], bh_[8][2], bl_[8][2];
            #pragma unroll
            for (int nt = 0; nt < 8; ++nt) {
                ldsm_x2(bh_[nt], sBh_ + (b_row + nt * 8) * 80 + bcol);
                ldsm_x2(bl_[nt], sBl_ + (b_row + nt * 8) * 80 + bcol);
            }
            #pragma unroll
            for (int mt = 0; mt < 4; ++mt)
                ldsm_x4(afr[mt], sAh_ + (a_row + mt * 16) * 80 + acol);
            #pragma unroll
            for (int mt = 0; mt < 4; ++mt)
                #pragma unroll
                for (int nt = 0; nt < 8; ++nt) {
                    mma16816(acc[mt][nt], afr[mt], bh_[nt]);
                    mma16816(acc[mt][nt], afr[mt], bl_[nt]);
                }
            #pragma unroll
            for (int mt = 0; mt < 4; ++mt)
                ldsm_x4(afr[mt], sAl_ + (a_row + mt * 16) * 80 + acol);   // reuse regs
            #pragma unroll
            for (int mt = 0; mt < 4; ++mt)
                #pragma unroll
                for (int nt = 0; nt < 8; ++nt)
                    mma16816(acc[mt][nt], afr[mt], bh_[nt]);
        }
    }

    // epilogue
    const int er = lane >> 2, ec = (lane & 3) << 1;
    #pragma unroll
    for (int mt = 0; mt < 4; ++mt) {
        #pragma unroll
        for (int nt = 0; nt < 8; ++nt) {
            int gr = row0 + wm * 64 + mt * 16 + er;
            int gc = col0 + wn * 64 + nt * 8 + ec;
            const float* cc = acc[mt][nt];
            #pragma unroll
            for (int half = 0; half < 2; ++half) {
                int r = gr + half * 8;
                float v0 = cc[half * 2 + 0], v1 = cc[half * 2 + 1];
                if (mode == 2) {
                    v0 = geluf_(v0 + bias[gc]);
                    v1 = geluf_(v1 + bias[gc + 1]);
                    bf16 h0 = __float2bfloat16(v0), h1 = __float2bfloat16(v1);
                    size_t o = (size_t)r * N + gc;
                    __nv_bfloat162 hp; hp.x = h0; hp.y = h1;
                    *(__nv_bfloat162*)(Oh + o) = hp;
                    __nv_bfloat162 lp;
                    lp.x = __float2bfloat16(v0 - __bfloat162float(h0));
                    lp.y = __float2bfloat16(v1 - __bfloat162float(h1));
                    *(__nv_bfloat162*)(Ol + o) = lp;
                } else {
                    if (bias) { v0 += bias[gc]; v1 += bias[gc + 1]; }
                    if (res) {
                        const float* rp = res + (size_t)r * N + gc;
                        v0 += rp[0]; v1 += rp[1];
                    }
                    float2 v; v.x = v0; v.y = v1;
                    *(float2*)(C + (size_t)r * N + gc) = v;
                }
            }
        }
    }
}

// ---------------- launch ----------------
extern "C" void kernel_launch(void* const* d_in, const int* in_sizes, int n_in,
                              void* d_out, int out_size) {
    const float* x       = (const float*)d_in[0];
    const float* w_in    = (const float*)d_in[1];
    const float* conv_w  = (const float*)d_in[2];
    const float* conv_b  = (const float*)d_in[3];
    const float* norm1_w = (const float*)d_in[4];
    const float* out_nw  = (const float*)d_in[5];
    const float* w_out   = (const float*)d_in[6];
    const float* norm2_w = (const float*)d_in[7];
    const float* ff_w1   = (const float*)d_in[8];
    const float* ff_b1   = (const float*)d_in[9];
    const float* ff_w2   = (const float*)d_in[10];
    const float* ff_b2   = (const float*)d_in[11];
    float* out = (float*)d_out;

    float *proj, *val, *par, *bcT, *scan, *x1;
    bf16 *h1h, *h1l, *ygh, *ygl, *h2h, *h2l, *ffh, *ffl;
    bf16 *winh, *winl, *woh, *wol, *w1h, *w1l, *w2h, *w2l;
    cudaGetSymbolAddress((void**)&proj, g_proj);
    cudaGetSymbolAddress((void**)&val,  g_val);
    cudaGetSymbolAddress((void**)&par,  g_par);
    cudaGetSymbolAddress((void**)&bcT,  g_bcT);
    cudaGetSymbolAddress((void**)&scan, g_scan);
    cudaGetSymbolAddress((void**)&x1,   g_x1);
    cudaGetSymbolAddress((void**)&h1h,  g_h1h);  cudaGetSymbolAddress((void**)&h1l, g_h1l);
    cudaGetSymbolAddress((void**)&ygh,  g_ygh);  cudaGetSymbolAddress((void**)&ygl, g_ygl);
    cudaGetSymbolAddress((void**)&h2h,  g_h2h);  cudaGetSymbolAddress((void**)&h2l, g_h2l);
    cudaGetSymbolAddress((void**)&ffh,  g_ffh);  cudaGetSymbolAddress((void**)&ffl, g_ffl);
    cudaGetSymbolAddress((void**)&winh, g_winh); cudaGetSymbolAddress((void**)&winl, g_winl);
    cudaGetSymbolAddress((void**)&woh,  g_woh);  cudaGetSymbolAddress((void**)&wol, g_wol);
    cudaGetSymbolAddress((void**)&w1h,  g_w1h);  cudaGetSymbolAddress((void**)&w1l, g_w1l);
    cudaGetSymbolAddress((void**)&w2h,  g_w2h);  cudaGetSymbolAddress((void**)&w2l, g_w2l);

    cudaFuncSetAttribute(gemm_mma, cudaFuncAttributeMaxDynamicSharedMemorySize, GEMM_SMEM);

    // weight splits (idempotent)
    split_kernel<<<(PROJ_OUT * 1024 + 255) / 256, 256>>>(w_in, winh, winl, PROJ_OUT * 1024);
    split_kernel<<<(1024 * 2048 + 255) / 256, 256>>>(w_out, woh, wol, 1024 * 2048);
    split_kernel<<<(4096 * 1024 + 255) / 256, 256>>>(ff_w1, w1h, w1l, 4096 * 1024);
    split_kernel<<<(1024 * 4096 + 255) / 256, 256>>>(ff_w2, w2h, w2l, 1024 * 4096);

    // 1. h1 = rmsnorm(x) (split)
    rmsnorm_split_kernel<<<BT, 256>>>(x, norm1_w, h1h, h1l, DMODEL);
    // 2. proj = h1 @ w_in^T  (4096 x 4224 x 1024)
    gemm_mma<<<dim3(PROJ_OUT / 128, BT / 256), 256, GEMM_SMEM>>>(h1h, h1l, winh, winl, nullptr, nullptr,
                                                      proj, nullptr, nullptr, PROJ_OUT, DMODEL, 0);
    // 3. fused conv+silu / params / bcpack
    prep_kernel<<<BT, 256>>>(proj, conv_w, conv_b, val, par, bcT);
    // 4. scan
    scan_kernel<<<2 * BQ * NHEADS, 512>>>(bcT, par, val, scan);
    // 5. yg = rmsnorm(scan * silu(gate)) (split)
    gated_norm_split_kernel<<<BT, 256>>>(proj, scan, out_nw, ygh, ygl);
    // 6. x1 = x + yg @ w_out^T  (4096 x 1024 x 2048)
    gemm_mma<<<dim3(DMODEL / 128, BT / 256), 256, GEMM_SMEM>>>(ygh, ygl, woh, wol, nullptr, x,
                                                    x1, nullptr, nullptr, DMODEL, DINNER, 1);
    // 7. h2 = rmsnorm(x1) (split)
    rmsnorm_split_kernel<<<BT, 256>>>(x1, norm2_w, h2h, h2l, DMODEL);
    // 8. ffa = split(gelu(h2 @ ff_w1^T + b1))  (4096 x 4096 x 1024)
    gemm_mma<<<dim3(DFF / 128, BT / 256), 256, GEMM_SMEM>>>(h2h, h2l, w1h, w1l, ff_b1, nullptr,
                                                 nullptr, ffh, ffl, DFF, DMODEL, 2);
    // 9. out = x1 + ffa @ ff_w2^T + b2  (4096 x 1024 x 4096)
    gemm_mma<<<dim3(DMODEL / 128, BT / 256), 256, GEMM_SMEM>>>(ffh, ffl, w2h, w2l, ff_b2, x1,
                                                    out, nullptr, nullptr, DMODEL, DFF, 1);
}